// round 14
// baseline (speedup 1.0000x reference)
#include <cuda_runtime.h>
#include <math.h>
#include <stdint.h>

#define BATCH 32
#define CH    128
#define SEQ   1024
#define RINN  256
#define RHH   512
#define OCC   128
#define MTOT  (BATCH*SEQ)   // 32768

typedef unsigned long long ull;

// ---------------- device scratch (no allocations allowed) ----------------
__device__ float g_scale[CH];
__device__ float g_shift[CH];
__device__ float g_winf[RINN*CH];
__device__ float g_binf[RINN];
__device__ float g_inp[MTOT*RINN];            // (B*L, 256)
__device__ float g_xgate[MTOT*RHH];           // (B*L, 512)
__device__ float g_outs[MTOT*RHH];            // (B*L, 512)

// ---------------- packed fp32x2 helpers ----------------------------------
__device__ __forceinline__ ull ffma2(ull a, ull b, ull c) {
    ull d; asm("fma.rn.f32x2 %0, %1, %2, %3;" : "=l"(d) : "l"(a), "l"(b), "l"(c)); return d;
}
__device__ __forceinline__ ull addf2(ull a, ull b) {
    ull d; asm("add.rn.f32x2 %0, %1, %2;" : "=l"(d) : "l"(a), "l"(b)); return d;
}
__device__ __forceinline__ ull pack2(float x, float y) {
    ull d; asm("mov.b64 %0, {%1, %2};" : "=l"(d) : "f"(x), "f"(y)); return d;
}
__device__ __forceinline__ ull dup2(float x) {
    ull d; asm("mov.b64 %0, {%1, %1};" : "=l"(d) : "f"(x)); return d;
}
__device__ __forceinline__ void unpack2(ull v, float& x, float& y) {
    asm("mov.b64 {%0, %1}, %2;" : "=f"(x), "=f"(y) : "l"(v));
}

// tanh(x) = 1 - 2/(e^{2x}+1), ex2.approx + rcp.approx (~1e-7 abs err)
__device__ __forceinline__ float tanh_fast(float x) {
    float e;
    asm("ex2.approx.f32 %0, %1;" : "=f"(e) : "f"(x * 2.8853900817779268f));
    float r;
    asm("rcp.approx.f32 %0, %1;" : "=f"(r) : "f"(e + 1.0f));
    return fmaf(-2.0f, r, 1.0f);
}

// ---------------- BN statistics -> scale/shift --------------------------
__global__ void bn_stats_k(const float* __restrict__ x,
                           const float* __restrict__ gamma,
                           const float* __restrict__ beta) {
    int c = blockIdx.x;
    int tid = threadIdx.x;
    float s = 0.f, s2 = 0.f;
    for (int i = tid; i < BATCH*SEQ; i += 256) {
        int b = i >> 10, p = i & 1023;
        float v = x[(((b*CH + c) << 10) + p)];
        s += v; s2 += v*v;
    }
    __shared__ float sh0[256], sh1[256];
    sh0[tid] = s; sh1[tid] = s2;
    __syncthreads();
    for (int o = 128; o > 0; o >>= 1) {
        if (tid < o) { sh0[tid] += sh0[tid+o]; sh1[tid] += sh1[tid+o]; }
        __syncthreads();
    }
    if (tid == 0) {
        const float inv = 1.0f / (float)(BATCH*SEQ);
        float mean = sh0[0] * inv;
        float var  = sh1[0] * inv - mean*mean;
        float sc = gamma[c] * rsqrtf(var + 1e-5f);
        g_scale[c] = sc;
        g_shift[c] = beta[c] - mean * sc;
    }
}

// ------------- fold BN into w_in / b_in ---------------------------------
__global__ void fold_k(const float* __restrict__ w_in,
                       const float* __restrict__ b_in) {
    int i = blockIdx.x;        // 0..255
    int c = threadIdx.x;       // 0..127
    float w = w_in[i*CH + c];
    g_winf[i*CH + c] = w * g_scale[c];
    float t = w * g_shift[c];
    __shared__ float red[128];
    red[c] = t;
    __syncthreads();
    for (int o = 64; o > 0; o >>= 1) {
        if (c < o) red[c] += red[c+o];
        __syncthreads();
    }
    if (c == 0) g_binf[i] = b_in[i] + red[0];
}

// -------- tiled fp32 GEMM, 128x128x16, 256 threads, 8x8 rtile, f32x2 ----
template<int MODE, int N, int K>
__global__ void __launch_bounds__(256)
gemm_k(const float* __restrict__ Aext,
       const float* __restrict__ Bext,
       const float* __restrict__ bias1,
       const float* __restrict__ bias2,
       float* __restrict__ Oext) {
    __shared__ float As[16*132];
    __shared__ float Bs[16*132];

    const int tid = threadIdx.x;
    const int mBase = blockIdx.x * 128;
    const int nBase = blockIdx.y * 128;

    const float* A  = (MODE == 1) ? g_inp : (MODE == 2 ? g_outs : Aext);
    const float* Bw = (MODE == 0) ? g_winf : Bext;

    ull acc2[8][4];
#pragma unroll
    for (int i = 0; i < 8; ++i)
#pragma unroll
        for (int j = 0; j < 4; ++j) acc2[i][j] = 0ull;

    const int tr = tid & 15;    // m quad
    const int tc = tid >> 4;    // n quad (0..15)

    for (int k0 = 0; k0 < K; k0 += 16) {
        // ---- A tile ----
        if (MODE == 0) {
            int c  = tid >> 4;            // k within tile
            int m4 = (tid & 15) * 4;
            int b  = mBase >> 10;
            int lb = mBase & 1023;
            const float* src = Aext + b*(CH*SEQ) + (k0 + c)*SEQ + lb;
            *(float4*)&As[c*132 + m4]      = *(const float4*)&src[m4];
            *(float4*)&As[c*132 + m4 + 64] = *(const float4*)&src[m4 + 64];
        } else {
            int rr = tid >> 2;
            int kq = (tid & 3) * 4;
            const float* s0 = A + (size_t)(mBase + rr)      * K + k0 + kq;
            const float* s1 = A + (size_t)(mBase + rr + 64) * K + k0 + kq;
            float4 v0 = *(const float4*)s0;
            float4 v1 = *(const float4*)s1;
            As[(kq+0)*132 + rr] = v0.x; As[(kq+1)*132 + rr] = v0.y;
            As[(kq+2)*132 + rr] = v0.z; As[(kq+3)*132 + rr] = v0.w;
            As[(kq+0)*132 + rr + 64] = v1.x; As[(kq+1)*132 + rr + 64] = v1.y;
            As[(kq+2)*132 + rr + 64] = v1.z; As[(kq+3)*132 + rr + 64] = v1.w;
        }
        // ---- B tile: 128 rows, thread covers 8 k ----
        {
            int n  = tid >> 1;            // 0..127
            int kq = (tid & 1) * 8;       // 0 or 8
            const float* bsrc = Bw + (size_t)(nBase + n) * K + k0 + kq;
            float4 v0 = *(const float4*)bsrc;
            float4 v1 = *(const float4*)(bsrc + 4);
            Bs[(kq+0)*132 + n] = v0.x; Bs[(kq+1)*132 + n] = v0.y;
            Bs[(kq+2)*132 + n] = v0.z; Bs[(kq+3)*132 + n] = v0.w;
            Bs[(kq+4)*132 + n] = v1.x; Bs[(kq+5)*132 + n] = v1.y;
            Bs[(kq+6)*132 + n] = v1.z; Bs[(kq+7)*132 + n] = v1.w;
        }
        __syncthreads();

#pragma unroll
        for (int k = 0; k < 16; ++k) {
            float4 a0 = *(const float4*)&As[k*132 + tr*4];
            float4 a1 = *(const float4*)&As[k*132 + tr*4 + 64];
            ulonglong2 bq0 = *(const ulonglong2*)&Bs[k*132 + tc*4];
            ulonglong2 bq1 = *(const ulonglong2*)&Bs[k*132 + tc*4 + 64];
            ull bp[4] = {bq0.x, bq0.y, bq1.x, bq1.y};
            float av[8] = {a0.x,a0.y,a0.z,a0.w,a1.x,a1.y,a1.z,a1.w};
#pragma unroll
            for (int i = 0; i < 8; ++i) {
                ull ad = dup2(av[i]);
#pragma unroll
                for (int j = 0; j < 4; ++j)
                    acc2[i][j] = ffma2(ad, bp[j], acc2[i][j]);
            }
        }
        __syncthreads();
    }

#pragma unroll
    for (int i = 0; i < 8; ++i) {
        int row = mBase + ((i < 4) ? (tr*4 + i) : (64 + tr*4 + (i-4)));
        float cv[8];
        unpack2(acc2[i][0], cv[0], cv[1]);
        unpack2(acc2[i][1], cv[2], cv[3]);
        unpack2(acc2[i][2], cv[4], cv[5]);
        unpack2(acc2[i][3], cv[6], cv[7]);
#pragma unroll
        for (int j = 0; j < 8; ++j) {
            int col = nBase + ((j < 4) ? (tc*4 + j) : (64 + tc*4 + (j-4)));
            float v = cv[j];
            if (MODE == 0) {
                v += g_binf[col];
                v = v - tanh_fast(v);
                g_inp[(size_t)row*N + col] = v;
            } else if (MODE == 1) {
                v += bias1[col] + bias2[col];
                g_xgate[(size_t)row*N + col] = v;
            } else {
                v += bias1[col];
                int b = row >> 10, l = row & 1023;
                Oext[(size_t)b*(OCC*SEQ) + (size_t)col*SEQ + l] = v;
            }
        }
    }
}

// ---------------- mbarrier / st.async helpers -----------------------------
__device__ __forceinline__ void mbar_init(uint32_t addr, unsigned count) {
    asm volatile("mbarrier.init.shared.b64 [%0], %1;" :: "r"(addr), "r"(count) : "memory");
}
__device__ __forceinline__ void mbar_expect_tx(uint32_t addr, unsigned bytes) {
    asm volatile("mbarrier.arrive.expect_tx.shared.b64 _, [%0], %1;"
                 :: "r"(addr), "r"(bytes) : "memory");
}
__device__ __forceinline__ void mbar_wait(uint32_t addr, unsigned parity) {
    unsigned done;
    asm volatile(
        "{\n\t.reg .pred P;\n\t"
        "mbarrier.try_wait.parity.acquire.cluster.shared::cta.b64 P, [%1], %2;\n\t"
        "selp.b32 %0, 1, 0, P;\n\t}"
        : "=r"(done) : "r"(addr), "r"(parity) : "memory");
    if (!done) {
        asm volatile(
            "{\n\t.reg .pred P;\n"
            "W%=:\n\t"
            "mbarrier.try_wait.parity.acquire.cluster.shared::cta.b64 P, [%0], %1, 0x989680;\n\t"
            "@P bra D%=;\n\t"
            "bra W%=;\n"
            "D%=:\n\t}"
            :: "r"(addr), "r"(parity) : "memory");
    }
}
// remote store that carries its own tx-completion to the DEST CTA's mbarrier
__device__ __forceinline__ void st_async64(uint32_t addr, ull v, uint32_t mbar) {
    asm volatile(
        "st.async.shared::cluster.mbarrier::complete_tx::bytes.b64 [%0], %1, [%2];"
        :: "r"(addr), "l"(v), "r"(mbar) : "memory");
}

// ---------------- clustered persistent RNN (st.async + per-src mbars) ----
// 16 clusters x 8 CTAs. Cluster cl handles batches {2cl, 2cl+1}.
// CTA rank r owns hidden units j in [r*64, r*64+64).
// Weights (64 x 512) in registers (packed j-pairs, f32x2).
// h exchanged via st.async into double buffers. KEY CHANGE vs R8: each
// destination keeps EIGHT mbarriers per buffer (one per source CTA), so the
// 64 tx-updates per (src,dst) stream serialize on their own word — 8
// independent chains in parallel instead of one 512-deep chain.
// Consumer: threads 0..7 each wait one mbar (HW-sleep), re-arm it for step
// l+2, then one __syncthreads publishes CTA-wide (and orders local buffer
// recycling). Expected tx per mbar per phase = 512 bytes (one source's h).
#define HSTRIDE 576   // 16 * 36
#define SRCTX   512u

__global__ void __launch_bounds__(256,1) __cluster_dims__(8,1,1)
rnn_k(const float* __restrict__ w_hh) {
    __shared__ __align__(16) float h_s[2][2][HSTRIDE];   // [buf][batch][...]
    __shared__ __align__(8) ull mb_s[16];                // [buf][src]

    const int tid  = threadIdx.x;
    const int warp = tid >> 5, lane = tid & 31;
    const int jq   = (warp << 1) | (lane & 1);   // 0..15: which quad of 4 j's
    const int kg   = lane >> 1;                  // 0..15: which 32-wide k slice
    uint32_t r; asm("mov.u32 %0, %%cluster_ctarank;" : "=r"(r));
    const int cl  = blockIdx.x >> 3;
    const int b0g = cl*2, b1g = cl*2 + 1;
    const int jcol  = (int)r*64 + jq*4;
    const int kbase = kg*32;

    // ---- weights into registers, packed per j-pair (lo=j0, hi=j1)
    ull w2[2][32];
#pragma unroll
    for (int jp = 0; jp < 2; ++jp) {
        const float* r0 = w_hh + (size_t)(jcol + jp*2) * RHH + kbase;
        const float* r1 = r0 + RHH;
#pragma unroll
        for (int q = 0; q < 8; ++q) {
            float4 a = *(const float4*)(r0 + q*4);
            float4 b = *(const float4*)(r1 + q*4);
            w2[jp][q*4+0] = pack2(a.x, b.x);
            w2[jp][q*4+1] = pack2(a.y, b.y);
            w2[jp][q*4+2] = pack2(a.z, b.z);
            w2[jp][q*4+3] = pack2(a.w, b.w);
        }
    }

    const uint32_t mb_local = (uint32_t)__cvta_generic_to_shared(&mb_s[0]);
    if (tid < 8) {
        mbar_init(mb_local + (0*8 + tid)*8, 1);
        mbar_init(mb_local + (1*8 + tid)*8, 1);
        // arm first phases: buf1 consumed at step 1, buf0 at step 2
        mbar_expect_tx(mb_local + (1*8 + tid)*8, SRCTX);
        mbar_expect_tx(mb_local + (0*8 + tid)*8, SRCTX);
    }
    // zero h buffer 0 (both batches)
    {
        float* z = &h_s[0][0][0];
        for (int i = tid; i < 2*HSTRIDE; i += 256) z[i] = 0.f;
    }
    __syncthreads();
    asm volatile("barrier.cluster.arrive.aligned;" ::: "memory");
    asm volatile("barrier.cluster.wait.aligned;" ::: "memory");

    // peer addresses (lane's target rank = kg, kg<8)
    uint32_t hbase = (uint32_t)__cvta_generic_to_shared(&h_s[0][0][0]);
    uint32_t hpeer = 0, mbpeer = 0;
    if (kg < 8) {
        asm("mapa.shared::cluster.u32 %0, %1, %2;"
            : "=r"(hpeer) : "r"(hbase), "r"((uint32_t)kg));
        asm("mapa.shared::cluster.u32 %0, %1, %2;"
            : "=r"(mbpeer) : "r"(mb_local), "r"((uint32_t)kg));
        mbpeer += (uint32_t)(r * 8);          // our src slot in peer's array
    }

    // write position of this thread's 4 j's inside an h buffer
    const int gidx = (int)r*2 + (jq >> 3);
    const int woff = (jq & 7) * 4;
    const uint32_t wbyte = (uint32_t)((gidx*36 + woff) * 4);

    // prefetch xgate for l = 0
    float4 xg0 = *(const float4*)&g_xgate[(size_t)(b0g << 10)*RHH + jcol];
    float4 xg1 = *(const float4*)&g_xgate[(size_t)(b1g << 10)*RHH + jcol];

    for (int l = 0; l < SEQ; ++l) {
        const int p = l & 1;

        // ---- wait for h_l: delegated per-source waits, then CTA publish.
        // The __syncthreads also orders this step's outgoing stores after
        // every local warp's reads of the buffer being recycled.
        if (l) {
            unsigned par = (unsigned)(((l - 1) >> 1) & 1);
            if (tid < 8) {
                uint32_t a = mb_local + (uint32_t)((p*8 + tid) * 8);
                mbar_wait(a, par);
                if (l < SEQ - 2)
                    mbar_expect_tx(a, SRCTX);   // re-arm for step l+2
            }
            __syncthreads();
        }

        const float* hb0 = &h_s[p][0][kg*36];
        const float* hb1 = &h_s[p][1][kg*36];

        ull a00 = 0ull, a01 = 0ull, a10 = 0ull, a11 = 0ull;  // [batch][jpair]
#pragma unroll
        for (int q = 0; q < 8; ++q) {
            float4 h0 = *(const float4*)(hb0 + q*4);
            float4 h1 = *(const float4*)(hb1 + q*4);
            ull hp;
            hp = dup2(h0.x); a00 = ffma2(hp, w2[0][q*4+0], a00); a01 = ffma2(hp, w2[1][q*4+0], a01);
            hp = dup2(h1.x); a10 = ffma2(hp, w2[0][q*4+0], a10); a11 = ffma2(hp, w2[1][q*4+0], a11);
            hp = dup2(h0.y); a00 = ffma2(hp, w2[0][q*4+1], a00); a01 = ffma2(hp, w2[1][q*4+1], a01);
            hp = dup2(h1.y); a10 = ffma2(hp, w2[0][q*4+1], a10); a11 = ffma2(hp, w2[1][q*4+1], a11);
            hp = dup2(h0.z); a00 = ffma2(hp, w2[0][q*4+2], a00); a01 = ffma2(hp, w2[1][q*4+2], a01);
            hp = dup2(h1.z); a10 = ffma2(hp, w2[0][q*4+2], a10); a11 = ffma2(hp, w2[1][q*4+2], a11);
            hp = dup2(h0.w); a00 = ffma2(hp, w2[0][q*4+3], a00); a01 = ffma2(hp, w2[1][q*4+3], a01);
            hp = dup2(h1.w); a10 = ffma2(hp, w2[0][q*4+3], a10); a11 = ffma2(hp, w2[1][q*4+3], a11);
        }

        // butterfly reduce over kg (lane bits 1..4); jq bit untouched
#pragma unroll
        for (int m = 2; m <= 16; m <<= 1) {
            a00 = addf2(a00, __shfl_xor_sync(0xffffffffu, a00, m));
            a01 = addf2(a01, __shfl_xor_sync(0xffffffffu, a01, m));
            a10 = addf2(a10, __shfl_xor_sync(0xffffffffu, a10, m));
            a11 = addf2(a11, __shfl_xor_sync(0xffffffffu, a11, m));
        }

        float s0, s1;
        unpack2(a00, s0, s1);
        float h00 = tanh_fast(s0 + xg0.x), h01 = tanh_fast(s1 + xg0.y);
        unpack2(a01, s0, s1);
        float h02 = tanh_fast(s0 + xg0.z), h03 = tanh_fast(s1 + xg0.w);
        unpack2(a10, s0, s1);
        float h10 = tanh_fast(s0 + xg1.x), h11 = tanh_fast(s1 + xg1.y);
        unpack2(a11, s0, s1);
        float h12 = tanh_fast(s0 + xg1.z), h13 = tanh_fast(s1 + xg1.w);

        if (l < SEQ - 1) {
            // broadcast new h to cluster CTA `kg` (buf p^1), crediting the
            // per-source mbarrier slot for our rank in the destination CTA
            if (kg < 8) {
                uint32_t base = hpeer + (uint32_t)(((p ^ 1) * 2) * HSTRIDE * 4) + wbyte;
                uint32_t mbt  = mbpeer + (uint32_t)((p ^ 1) * 64);
                st_async64(base,                   pack2(h00, h01), mbt);
                st_async64(base + 8,               pack2(h02, h03), mbt);
                st_async64(base + HSTRIDE*4,       pack2(h10, h11), mbt);
                st_async64(base + HSTRIDE*4 + 8,   pack2(h12, h13), mbt);
            }
            // prefetch next step's xgate (overlaps store propagation)
            int l1 = l + 1;
            xg0 = *(const float4*)&g_xgate[(size_t)((b0g << 10) | l1)*RHH + jcol];
            xg1 = *(const float4*)&g_xgate[(size_t)((b1g << 10) | l1)*RHH + jcol];
        }

        if (kg == 8) {  // one writer lane-pair per jq: persist outputs
            size_t row0 = (size_t)((b0g << 10) | l);
            size_t row1 = (size_t)((b1g << 10) | l);
            *(float4*)&g_outs[row0*RHH + jcol] = make_float4(h00, h01, h02, h03);
            *(float4*)&g_outs[row1*RHH + jcol] = make_float4(h10, h11, h12, h13);
        }
    }

    // keep SMEM alive until all peers are done with remote ops
    asm volatile("barrier.cluster.arrive.aligned;" ::: "memory");
    asm volatile("barrier.cluster.wait.aligned;" ::: "memory");
}

// ---------------- launch ---------------------------------------------------
extern "C" void kernel_launch(void* const* d_in, const int* in_sizes, int n_in,
                              void* d_out, int out_size) {
    const float* x     = (const float*)d_in[0];
    const float* gamma = (const float*)d_in[1];
    const float* beta  = (const float*)d_in[2];
    const float* w_in  = (const float*)d_in[3];
    const float* b_in  = (const float*)d_in[4];
    const float* w_ih  = (const float*)d_in[5];
    const float* b_ih  = (const float*)d_in[6];
    const float* w_hh  = (const float*)d_in[7];
    const float* b_hh  = (const float*)d_in[8];
    const float* w_out = (const float*)d_in[9];
    const float* b_out = (const float*)d_in[10];
    float* out = (float*)d_out;

    bn_stats_k<<<CH, 256>>>(x, gamma, beta);
    fold_k<<<RINN, 128>>>(w_in, b_in);

    dim3 g1(MTOT/128, RINN/128);   // (256, 2)
    gemm_k<0, RINN, CH><<<g1, 256>>>(x, nullptr, nullptr, nullptr, nullptr);

    dim3 g2(MTOT/128, RHH/128);    // (256, 4)
    gemm_k<1, RHH, RINN><<<g2, 256>>>(nullptr, w_ih, b_ih, b_hh, nullptr);

    rnn_k<<<128, 256>>>(w_hh);

    dim3 g4(MTOT/128, OCC/128);    // (256, 1)
    gemm_k<2, OCC, RHH><<<g4, 256>>>(nullptr, w_out, b_out, nullptr, out);
}

// round 15
// speedup vs baseline: 1.8989x; 1.8989x over previous
#include <cuda_runtime.h>
#include <math.h>
#include <stdint.h>

#define BATCH 32
#define CH    128
#define SEQ   1024
#define RINN  256
#define RHH   512
#define OCC   128
#define MTOT  (BATCH*SEQ)   // 32768

typedef unsigned long long ull;

// ---------------- device scratch (no allocations allowed) ----------------
__device__ float g_scale[CH];
__device__ float g_shift[CH];
__device__ float g_winf[RINN*CH];
__device__ float g_binf[RINN];
__device__ float g_inp[MTOT*RINN];            // (B*L, 256)
__device__ float g_xgate[MTOT*RHH];           // (B*L, 512)
__device__ float g_outs[MTOT*RHH];            // (B*L, 512)

// ---------------- packed fp32x2 helpers ----------------------------------
__device__ __forceinline__ ull ffma2(ull a, ull b, ull c) {
    ull d; asm("fma.rn.f32x2 %0, %1, %2, %3;" : "=l"(d) : "l"(a), "l"(b), "l"(c)); return d;
}
__device__ __forceinline__ ull addf2(ull a, ull b) {
    ull d; asm("add.rn.f32x2 %0, %1, %2;" : "=l"(d) : "l"(a), "l"(b)); return d;
}
__device__ __forceinline__ ull pack2(float x, float y) {
    ull d; asm("mov.b64 %0, {%1, %2};" : "=l"(d) : "f"(x), "f"(y)); return d;
}
__device__ __forceinline__ ull dup2(float x) {
    ull d; asm("mov.b64 %0, {%1, %1};" : "=l"(d) : "f"(x)); return d;
}
__device__ __forceinline__ void unpack2(ull v, float& x, float& y) {
    asm("mov.b64 {%0, %1}, %2;" : "=f"(x), "=f"(y) : "l"(v));
}

// tanh(x) = 1 - 2/(e^{2x}+1), ex2.approx + rcp.approx (~1e-7 abs err)
__device__ __forceinline__ float tanh_fast(float x) {
    float e;
    asm("ex2.approx.f32 %0, %1;" : "=f"(e) : "f"(x * 2.8853900817779268f));
    float r;
    asm("rcp.approx.f32 %0, %1;" : "=f"(r) : "f"(e + 1.0f));
    return fmaf(-2.0f, r, 1.0f);
}

// ---------------- BN statistics -> scale/shift --------------------------
__global__ void bn_stats_k(const float* __restrict__ x,
                           const float* __restrict__ gamma,
                           const float* __restrict__ beta) {
    int c = blockIdx.x;
    int tid = threadIdx.x;
    float s = 0.f, s2 = 0.f;
    for (int i = tid; i < BATCH*SEQ; i += 256) {
        int b = i >> 10, p = i & 1023;
        float v = x[(((b*CH + c) << 10) + p)];
        s += v; s2 += v*v;
    }
    __shared__ float sh0[256], sh1[256];
    sh0[tid] = s; sh1[tid] = s2;
    __syncthreads();
    for (int o = 128; o > 0; o >>= 1) {
        if (tid < o) { sh0[tid] += sh0[tid+o]; sh1[tid] += sh1[tid+o]; }
        __syncthreads();
    }
    if (tid == 0) {
        const float inv = 1.0f / (float)(BATCH*SEQ);
        float mean = sh0[0] * inv;
        float var  = sh1[0] * inv - mean*mean;
        float sc = gamma[c] * rsqrtf(var + 1e-5f);
        g_scale[c] = sc;
        g_shift[c] = beta[c] - mean * sc;
    }
}

// ------------- fold BN into w_in / b_in ---------------------------------
__global__ void fold_k(const float* __restrict__ w_in,
                       const float* __restrict__ b_in) {
    int i = blockIdx.x;        // 0..255
    int c = threadIdx.x;       // 0..127
    float w = w_in[i*CH + c];
    g_winf[i*CH + c] = w * g_scale[c];
    float t = w * g_shift[c];
    __shared__ float red[128];
    red[c] = t;
    __syncthreads();
    for (int o = 64; o > 0; o >>= 1) {
        if (c < o) red[c] += red[c+o];
        __syncthreads();
    }
    if (c == 0) g_binf[i] = b_in[i] + red[0];
}

// -------- tiled fp32 GEMM, 128x128x16, software-pipelined (double buf) ---
template<int MODE, int N, int K>
__global__ void __launch_bounds__(256, 2)
gemm_k(const float* __restrict__ Aext,
       const float* __restrict__ Bext,
       const float* __restrict__ bias1,
       const float* __restrict__ bias2,
       float* __restrict__ Oext) {
    __shared__ float As[2][16*132];
    __shared__ float Bs[2][16*132];

    const int tid = threadIdx.x;
    const int mBase = blockIdx.x * 128;
    const int nBase = blockIdx.y * 128;

    const float* A  = (MODE == 1) ? g_inp : (MODE == 2 ? g_outs : Aext);
    const float* Bw = (MODE == 0) ? g_winf : Bext;

    // ---- per-thread source pointers
    // A (MODE 0): [k][m] direct copy
    const int c0  = tid >> 4;             // k row within tile
    const int m4  = (tid & 15) * 4;
    const float* asrc0 = (MODE == 0)
        ? Aext + (mBase >> 10)*(CH*SEQ) + c0*SEQ + (mBase & 1023) : nullptr;
    // A (MODE 1/2): transpose via regs
    const int rr  = tid >> 2;
    const int kqa = (tid & 3) * 4;
    const float* asrc1 = (MODE != 0)
        ? A + (size_t)(mBase + rr) * K + kqa : nullptr;
    // B: transpose via regs
    const int nn  = tid >> 1;
    const int kqb = (tid & 1) * 8;
    const float* bsrc = Bw + (size_t)(nBase + nn) * K + kqb;

    float4 ra0, ra1, rb0, rb1;

    ull acc2[8][4];
#pragma unroll
    for (int i = 0; i < 8; ++i)
#pragma unroll
        for (int j = 0; j < 4; ++j) acc2[i][j] = 0ull;

    const int tr = tid & 15;    // m quad
    const int tc = tid >> 4;    // n quad (0..15)

#define G_LOAD(k0) do {                                                     \
        if (MODE == 0) {                                                    \
            ra0 = *(const float4*)(asrc0 + (size_t)(k0)*SEQ + m4);          \
            ra1 = *(const float4*)(asrc0 + (size_t)(k0)*SEQ + m4 + 64);     \
        } else {                                                            \
            ra0 = *(const float4*)(asrc1 + (k0));                           \
            ra1 = *(const float4*)(asrc1 + (size_t)64*K + (k0));            \
        }                                                                   \
        rb0 = *(const float4*)(bsrc + (k0));                                \
        rb1 = *(const float4*)(bsrc + (k0) + 4);                            \
    } while (0)

#define S_STORE(buf) do {                                                   \
        if (MODE == 0) {                                                    \
            *(float4*)&As[buf][c0*132 + m4]      = ra0;                     \
            *(float4*)&As[buf][c0*132 + m4 + 64] = ra1;                     \
        } else {                                                            \
            As[buf][(kqa+0)*132 + rr] = ra0.x; As[buf][(kqa+1)*132 + rr] = ra0.y; \
            As[buf][(kqa+2)*132 + rr] = ra0.z; As[buf][(kqa+3)*132 + rr] = ra0.w; \
            As[buf][(kqa+0)*132 + rr + 64] = ra1.x; As[buf][(kqa+1)*132 + rr + 64] = ra1.y; \
            As[buf][(kqa+2)*132 + rr + 64] = ra1.z; As[buf][(kqa+3)*132 + rr + 64] = ra1.w; \
        }                                                                   \
        Bs[buf][(kqb+0)*132 + nn] = rb0.x; Bs[buf][(kqb+1)*132 + nn] = rb0.y; \
        Bs[buf][(kqb+2)*132 + nn] = rb0.z; Bs[buf][(kqb+3)*132 + nn] = rb0.w; \
        Bs[buf][(kqb+4)*132 + nn] = rb1.x; Bs[buf][(kqb+5)*132 + nn] = rb1.y; \
        Bs[buf][(kqb+6)*132 + nn] = rb1.z; Bs[buf][(kqb+7)*132 + nn] = rb1.w; \
    } while (0)

    const int T = K / 16;
    G_LOAD(0);
    S_STORE(0);
    __syncthreads();

    for (int t = 0; t < T; ++t) {
        const int cur = t & 1;
        const bool more = (t + 1 < T);
        if (more) G_LOAD((t + 1) * 16);

#pragma unroll
        for (int k = 0; k < 16; ++k) {
            float4 a0 = *(const float4*)&As[cur][k*132 + tr*4];
            float4 a1 = *(const float4*)&As[cur][k*132 + tr*4 + 64];
            ulonglong2 bq0 = *(const ulonglong2*)&Bs[cur][k*132 + tc*4];
            ulonglong2 bq1 = *(const ulonglong2*)&Bs[cur][k*132 + tc*4 + 64];
            ull bp[4] = {bq0.x, bq0.y, bq1.x, bq1.y};
            float av[8] = {a0.x,a0.y,a0.z,a0.w,a1.x,a1.y,a1.z,a1.w};
#pragma unroll
            for (int i = 0; i < 8; ++i) {
                ull ad = dup2(av[i]);
#pragma unroll
                for (int j = 0; j < 4; ++j)
                    acc2[i][j] = ffma2(ad, bp[j], acc2[i][j]);
            }
        }

        if (more) {
            S_STORE((t + 1) & 1);
            __syncthreads();
        }
    }
#undef G_LOAD
#undef S_STORE

#pragma unroll
    for (int i = 0; i < 8; ++i) {
        int row = mBase + ((i < 4) ? (tr*4 + i) : (64 + tr*4 + (i-4)));
        float cv[8];
        unpack2(acc2[i][0], cv[0], cv[1]);
        unpack2(acc2[i][1], cv[2], cv[3]);
        unpack2(acc2[i][2], cv[4], cv[5]);
        unpack2(acc2[i][3], cv[6], cv[7]);
#pragma unroll
        for (int j = 0; j < 8; ++j) {
            int col = nBase + ((j < 4) ? (tc*4 + j) : (64 + tc*4 + (j-4)));
            float v = cv[j];
            if (MODE == 0) {
                v += g_binf[col];
                v = v - tanh_fast(v);
                g_inp[(size_t)row*N + col] = v;
            } else if (MODE == 1) {
                v += bias1[col] + bias2[col];
                g_xgate[(size_t)row*N + col] = v;
            } else {
                v += bias1[col];
                int b = row >> 10, l = row & 1023;
                Oext[(size_t)b*(OCC*SEQ) + (size_t)col*SEQ + l] = v;
            }
        }
    }
}

// ---------------- mbarrier helpers ----------------------------------------
__device__ __forceinline__ void mbar_init(uint32_t addr, unsigned count) {
    asm volatile("mbarrier.init.shared.b64 [%0], %1;" :: "r"(addr), "r"(count) : "memory");
}
__device__ __forceinline__ void mbar_expect_tx(uint32_t addr, unsigned bytes) {
    asm volatile("mbarrier.arrive.expect_tx.shared.b64 _, [%0], %1;"
                 :: "r"(addr), "r"(bytes) : "memory");
}
__device__ __forceinline__ void mbar_wait(uint32_t addr, unsigned parity) {
    unsigned done;
    asm volatile(
        "{\n\t.reg .pred P;\n\t"
        "mbarrier.try_wait.parity.acquire.cluster.shared::cta.b64 P, [%1], %2;\n\t"
        "selp.b32 %0, 1, 0, P;\n\t}"
        : "=r"(done) : "r"(addr), "r"(parity) : "memory");
    if (!done) {
        asm volatile(
            "{\n\t.reg .pred P;\n"
            "W%=:\n\t"
            "mbarrier.try_wait.parity.acquire.cluster.shared::cta.b64 P, [%0], %1, 0x989680;\n\t"
            "@P bra D%=;\n\t"
            "bra W%=;\n"
            "D%=:\n\t}"
            :: "r"(addr), "r"(parity) : "memory");
    }
}
// bulk DSMEM copy: local smem -> peer CTA smem, credits peer's mbarrier
__device__ __forceinline__ void bulk_copy_cluster(uint32_t dst, uint32_t src,
                                                  unsigned bytes, uint32_t mbar) {
    asm volatile(
        "cp.async.bulk.shared::cluster.shared::cta.mbarrier::complete_tx::bytes "
        "[%0], [%1], %2, [%3];"
        :: "r"(dst), "r"(src), "r"(bytes), "r"(mbar) : "memory");
}

// ---------------- clustered persistent RNN (R9 + self-STS) ---------------
// 16 clusters x 8 CTAs. Cluster cl handles batches {2cl, 2cl+1}.
// CTA rank r owns hidden units j in [r*64, r*64+64).
// Weights (64 x 512) in registers (packed j-pairs, f32x2) — R9 dup2 loop.
// Exchange: stage 128 floats; 7 REMOTE 512B bulk copies (self block written
// by plain STS into local h_s[p^1], ordered by the pre-bulk __syncthreads).
// Dest mbarrier sees 7 tx completions = 3584 bytes per phase.
// h buffer layout: [buf][src r: 132 floats = b0(64) b1(64) pad(4)].
#define SRCBLK 132            // floats per source block
#define HBUFW  (8*SRCBLK)     // 1056 floats per buffer
#define TXBYTES 3584u         // 7 remote sources x 512B

__global__ void __launch_bounds__(256,1) __cluster_dims__(8,1,1)
rnn_k(const float* __restrict__ w_hh) {
    __shared__ __align__(16) float h_s[2][HBUFW];     // [buf][8 src blocks]
    __shared__ __align__(16) float stage[2][128];     // double-buffered staging
    __shared__ __align__(8) ull mb_s[2];              // one mbarrier per buf

    const int tid  = threadIdx.x;
    const int warp = tid >> 5, lane = tid & 31;
    const int jq   = (warp << 1) | (lane & 1);   // 0..15: which quad of 4 j's
    const int kg   = lane >> 1;                  // 0..15: which 32-wide k slice
    uint32_t r; asm("mov.u32 %0, %%cluster_ctarank;" : "=r"(r));
    const int cl  = blockIdx.x >> 3;
    const int b0g = cl*2, b1g = cl*2 + 1;
    const int jcol  = (int)r*64 + jq*4;
    const int kbase = kg*32;

    // ---- weights into registers, packed per j-pair (lo=j0, hi=j1)
    ull w2[2][32];
#pragma unroll
    for (int jp = 0; jp < 2; ++jp) {
        const float* r0 = w_hh + (size_t)(jcol + jp*2) * RHH + kbase;
        const float* r1 = r0 + RHH;
#pragma unroll
        for (int q = 0; q < 8; ++q) {
            float4 a = *(const float4*)(r0 + q*4);
            float4 b = *(const float4*)(r1 + q*4);
            w2[jp][q*4+0] = pack2(a.x, b.x);
            w2[jp][q*4+1] = pack2(a.y, b.y);
            w2[jp][q*4+2] = pack2(a.z, b.z);
            w2[jp][q*4+3] = pack2(a.w, b.w);
        }
    }

    const uint32_t mb_local = (uint32_t)__cvta_generic_to_shared(&mb_s[0]);
    if (tid == 0) {
        mbar_init(mb_local,     1);
        mbar_init(mb_local + 8, 1);
        // arm first phases: mb[1] consumed at step 1, mb[0] at step 2
        mbar_expect_tx(mb_local + 8, TXBYTES);
        mbar_expect_tx(mb_local,     TXBYTES);
    }
    // zero h buffer 0
    for (int i = tid; i < HBUFW; i += 256) h_s[0][i] = 0.f;
    __syncthreads();
    asm volatile("barrier.cluster.arrive.aligned;" ::: "memory");
    asm volatile("barrier.cluster.wait.aligned;" ::: "memory");

    // peer addresses for bulk issue (thread tid<8 targets rank tid; skip self)
    const uint32_t h_base     = (uint32_t)__cvta_generic_to_shared(&h_s[0][0]);
    const uint32_t stage_base = (uint32_t)__cvta_generic_to_shared(&stage[0][0]);
    uint32_t hpeer = 0, mbpeer = 0;
    if (tid < 8) {
        asm("mapa.shared::cluster.u32 %0, %1, %2;"
            : "=r"(hpeer) : "r"(h_base), "r"((uint32_t)tid));
        asm("mapa.shared::cluster.u32 %0, %1, %2;"
            : "=r"(mbpeer) : "r"(mb_local), "r"((uint32_t)tid));
        hpeer += (uint32_t)(r * (SRCBLK*4));   // my block in peer's buffer
    }

    // prefetch xgate for l = 0
    float4 xg0 = *(const float4*)&g_xgate[(size_t)(b0g << 10)*RHH + jcol];
    float4 xg1 = *(const float4*)&g_xgate[(size_t)(b1g << 10)*RHH + jcol];

    for (int l = 0; l < SEQ; ++l) {
        const int p = l & 1;

        // ---- wait for h_l (bulks issued during step l-1); re-arm phase
        if (l) {
            unsigned par = (unsigned)(((l - 1) >> 1) & 1);
            mbar_wait(mb_local + p*8, par);
            if (tid == 0 && l < SEQ - 2)
                mbar_expect_tx(mb_local + p*8, TXBYTES);  // phase for step l+2
        }

        const float* hb0 = &h_s[p][(kg>>1)*SRCBLK + (kg&1)*32];
        const float* hb1 = hb0 + 64;

        ull a00 = 0ull, a01 = 0ull, a10 = 0ull, a11 = 0ull;  // [batch][jpair]
#pragma unroll
        for (int q = 0; q < 8; ++q) {
            float4 h0 = *(const float4*)(hb0 + q*4);
            float4 h1 = *(const float4*)(hb1 + q*4);
            ull hp;
            hp = dup2(h0.x); a00 = ffma2(hp, w2[0][q*4+0], a00); a01 = ffma2(hp, w2[1][q*4+0], a01);
            hp = dup2(h1.x); a10 = ffma2(hp, w2[0][q*4+0], a10); a11 = ffma2(hp, w2[1][q*4+0], a11);
            hp = dup2(h0.y); a00 = ffma2(hp, w2[0][q*4+1], a00); a01 = ffma2(hp, w2[1][q*4+1], a01);
            hp = dup2(h1.y); a10 = ffma2(hp, w2[0][q*4+1], a10); a11 = ffma2(hp, w2[1][q*4+1], a11);
            hp = dup2(h0.z); a00 = ffma2(hp, w2[0][q*4+2], a00); a01 = ffma2(hp, w2[1][q*4+2], a01);
            hp = dup2(h1.z); a10 = ffma2(hp, w2[0][q*4+2], a10); a11 = ffma2(hp, w2[1][q*4+2], a11);
            hp = dup2(h0.w); a00 = ffma2(hp, w2[0][q*4+3], a00); a01 = ffma2(hp, w2[1][q*4+3], a01);
            hp = dup2(h1.w); a10 = ffma2(hp, w2[0][q*4+3], a10); a11 = ffma2(hp, w2[1][q*4+3], a11);
        }

        // butterfly reduce over kg (lane bits 1..4); jq bit untouched
#pragma unroll
        for (int m = 2; m <= 16; m <<= 1) {
            a00 = addf2(a00, __shfl_xor_sync(0xffffffffu, a00, m));
            a01 = addf2(a01, __shfl_xor_sync(0xffffffffu, a01, m));
            a10 = addf2(a10, __shfl_xor_sync(0xffffffffu, a10, m));
            a11 = addf2(a11, __shfl_xor_sync(0xffffffffu, a11, m));
        }

        float s0, s1;
        unpack2(a00, s0, s1);
        float h00 = tanh_fast(s0 + xg0.x), h01 = tanh_fast(s1 + xg0.y);
        unpack2(a01, s0, s1);
        float h02 = tanh_fast(s0 + xg0.z), h03 = tanh_fast(s1 + xg0.w);
        unpack2(a10, s0, s1);
        float h10 = tanh_fast(s0 + xg1.x), h11 = tanh_fast(s1 + xg1.y);
        unpack2(a11, s0, s1);
        float h12 = tanh_fast(s0 + xg1.z), h13 = tanh_fast(s1 + xg1.w);

        // stage this CTA's 128 result floats (writers: lanes 0,1 per warp)
        if (lane < 2) {
            *(float4*)&stage[p][jq*4]      = make_float4(h00, h01, h02, h03);
            *(float4*)&stage[p][64 + jq*4] = make_float4(h10, h11, h12, h13);
        }
        // self block: plain STS into next buffer (lanes 2,3 per warp).
        // Ordered for next-step local readers by the __syncthreads below.
        if (kg == 1 && l < SEQ - 1) {
            float* own = &h_s[p ^ 1][(int)r*SRCBLK];
            *(float4*)&own[jq*4]      = make_float4(h00, h01, h02, h03);
            *(float4*)&own[64 + jq*4] = make_float4(h10, h11, h12, h13);
        }
        if (kg == 8) {  // persist outputs (lanes 16,17 per warp)
            size_t row0 = (size_t)((b0g << 10) | l);
            size_t row1 = (size_t)((b1g << 10) | l);
            *(float4*)&g_outs[row0*RHH + jcol] = make_float4(h00, h01, h02, h03);
            *(float4*)&g_outs[row1*RHH + jcol] = make_float4(h10, h11, h12, h13);
        }

        if (l < SEQ - 1) {
            __syncthreads();     // staging + self STS done; all reads of buf p done
            if (tid < 8 && tid != (int)r) {
                asm volatile("fence.proxy.async.shared::cta;" ::: "memory");
                bulk_copy_cluster(hpeer + (uint32_t)((p ^ 1) * (HBUFW*4)),
                                  stage_base + (uint32_t)(p * 512),
                                  512u,
                                  mbpeer + (uint32_t)((p ^ 1) * 8));
            }
            // prefetch next step's xgate (overlaps bulk propagation)
            int l1 = l + 1;
            xg0 = *(const float4*)&g_xgate[(size_t)((b0g << 10) | l1)*RHH + jcol];
            xg1 = *(const float4*)&g_xgate[(size_t)((b1g << 10) | l1)*RHH + jcol];
        }
    }

    // keep SMEM alive until all peers are done with remote ops
    asm volatile("barrier.cluster.arrive.aligned;" ::: "memory");
    asm volatile("barrier.cluster.wait.aligned;" ::: "memory");
}

// ---------------- launch ---------------------------------------------------
extern "C" void kernel_launch(void* const* d_in, const int* in_sizes, int n_in,
                              void* d_out, int out_size) {
    const float* x     = (const float*)d_in[0];
    const float* gamma = (const float*)d_in[1];
    const float* beta  = (const float*)d_in[2];
    const float* w_in  = (const float*)d_in[3];
    const float* b_in  = (const float*)d_in[4];
    const float* w_ih  = (const float*)d_in[5];
    const float* b_ih  = (const float*)d_in[6];
    const float* w_hh  = (const float*)d_in[7];
    const float* b_hh  = (const float*)d_in[8];
    const float* w_out = (const float*)d_in[9];
    const float* b_out = (const float*)d_in[10];
    float* out = (float*)d_out;

    bn_stats_k<<<CH, 256>>>(x, gamma, beta);
    fold_k<<<RINN, 128>>>(w_in, b_in);

    dim3 g1(MTOT/128, RINN/128);   // (256, 2)
    gemm_k<0, RINN, CH><<<g1, 256>>>(x, nullptr, nullptr, nullptr, nullptr);

    dim3 g2(MTOT/128, RHH/128);    // (256, 4)
    gemm_k<1, RHH, RINN><<<g2, 256>>>(nullptr, w_ih, b_ih, b_hh, nullptr);

    rnn_k<<<128, 256>>>(w_hh);

    dim3 g4(MTOT/128, OCC/128);    // (256, 1)
    gemm_k<2, OCC, RHH><<<g4, 256>>>(nullptr, w_out, b_out, nullptr, out);
}

// round 16
// speedup vs baseline: 2.0487x; 1.0789x over previous
#include <cuda_runtime.h>
#include <math.h>
#include <stdint.h>

#define BATCH 32
#define CH    128
#define SEQ   1024
#define RINN  256
#define RHH   512
#define OCC   128
#define MTOT  (BATCH*SEQ)   // 32768

typedef unsigned long long ull;

// ---------------- device scratch (no allocations allowed) ----------------
__device__ float g_scale[CH];
__device__ float g_shift[CH];
__device__ float g_winf[RINN*CH];
__device__ float g_binf[RINN];
__device__ float g_inp[MTOT*RINN];            // (B*L, 256)
__device__ float g_xgate[MTOT*RHH];           // (B*L, 512)
__device__ float g_outs[MTOT*RHH];            // (B*L, 512)

// ---------------- packed fp32x2 helpers ----------------------------------
__device__ __forceinline__ ull ffma2(ull a, ull b, ull c) {
    ull d; asm("fma.rn.f32x2 %0, %1, %2, %3;" : "=l"(d) : "l"(a), "l"(b), "l"(c)); return d;
}
__device__ __forceinline__ ull addf2(ull a, ull b) {
    ull d; asm("add.rn.f32x2 %0, %1, %2;" : "=l"(d) : "l"(a), "l"(b)); return d;
}
__device__ __forceinline__ ull pack2(float x, float y) {
    ull d; asm("mov.b64 %0, {%1, %2};" : "=l"(d) : "f"(x), "f"(y)); return d;
}
__device__ __forceinline__ ull dup2(float x) {
    ull d; asm("mov.b64 %0, {%1, %1};" : "=l"(d) : "f"(x)); return d;
}
__device__ __forceinline__ void unpack2(ull v, float& x, float& y) {
    asm("mov.b64 {%0, %1}, %2;" : "=f"(x), "=f"(y) : "l"(v));
}

// tanh(x) = 1 - 2/(e^{2x}+1), ex2.approx + rcp.approx (~1e-7 abs err)
__device__ __forceinline__ float tanh_fast(float x) {
    float e;
    asm("ex2.approx.f32 %0, %1;" : "=f"(e) : "f"(x * 2.8853900817779268f));
    float r;
    asm("rcp.approx.f32 %0, %1;" : "=f"(r) : "f"(e + 1.0f));
    return fmaf(-2.0f, r, 1.0f);
}

// ---------------- BN statistics -> scale/shift --------------------------
__global__ void bn_stats_k(const float* __restrict__ x,
                           const float* __restrict__ gamma,
                           const float* __restrict__ beta) {
    int c = blockIdx.x;
    int tid = threadIdx.x;
    float s = 0.f, s2 = 0.f;
    for (int i = tid; i < BATCH*SEQ; i += 256) {
        int b = i >> 10, p = i & 1023;
        float v = x[(((b*CH + c) << 10) + p)];
        s += v; s2 += v*v;
    }
    __shared__ float sh0[256], sh1[256];
    sh0[tid] = s; sh1[tid] = s2;
    __syncthreads();
    for (int o = 128; o > 0; o >>= 1) {
        if (tid < o) { sh0[tid] += sh0[tid+o]; sh1[tid] += sh1[tid+o]; }
        __syncthreads();
    }
    if (tid == 0) {
        const float inv = 1.0f / (float)(BATCH*SEQ);
        float mean = sh0[0] * inv;
        float var  = sh1[0] * inv - mean*mean;
        float sc = gamma[c] * rsqrtf(var + 1e-5f);
        g_scale[c] = sc;
        g_shift[c] = beta[c] - mean * sc;
    }
}

// ------------- fold BN into w_in / b_in ---------------------------------
__global__ void fold_k(const float* __restrict__ w_in,
                       const float* __restrict__ b_in) {
    int i = blockIdx.x;        // 0..255
    int c = threadIdx.x;       // 0..127
    float w = w_in[i*CH + c];
    g_winf[i*CH + c] = w * g_scale[c];
    float t = w * g_shift[c];
    __shared__ float red[128];
    red[c] = t;
    __syncthreads();
    for (int o = 64; o > 0; o >>= 1) {
        if (c < o) red[c] += red[c+o];
        __syncthreads();
    }
    if (c == 0) g_binf[i] = b_in[i] + red[0];
}

// -------- tiled fp32 GEMM, 128x128x16, software-pipelined (double buf) ---
template<int MODE, int N, int K>
__global__ void __launch_bounds__(256, 2)
gemm_k(const float* __restrict__ Aext,
       const float* __restrict__ Bext,
       const float* __restrict__ bias1,
       const float* __restrict__ bias2,
       float* __restrict__ Oext) {
    __shared__ float As[2][16*132];
    __shared__ float Bs[2][16*132];

    const int tid = threadIdx.x;
    const int mBase = blockIdx.x * 128;
    const int nBase = blockIdx.y * 128;

    const float* A  = (MODE == 1) ? g_inp : (MODE == 2 ? g_outs : Aext);
    const float* Bw = (MODE == 0) ? g_winf : Bext;

    // ---- per-thread source pointers
    const int c0  = tid >> 4;             // k row within tile (MODE 0)
    const int m4  = (tid & 15) * 4;
    const float* asrc0 = (MODE == 0)
        ? Aext + (mBase >> 10)*(CH*SEQ) + c0*SEQ + (mBase & 1023) : nullptr;
    const int rr  = tid >> 2;
    const int kqa = (tid & 3) * 4;
    const float* asrc1 = (MODE != 0)
        ? A + (size_t)(mBase + rr) * K + kqa : nullptr;
    const int nn  = tid >> 1;
    const int kqb = (tid & 1) * 8;
    const float* bsrc = Bw + (size_t)(nBase + nn) * K + kqb;

    float4 ra0, ra1, rb0, rb1;

    ull acc2[8][4];
#pragma unroll
    for (int i = 0; i < 8; ++i)
#pragma unroll
        for (int j = 0; j < 4; ++j) acc2[i][j] = 0ull;

    const int tr = tid & 15;    // m quad
    const int tc = tid >> 4;    // n quad (0..15)

#define G_LOAD(k0) do {                                                     \
        if (MODE == 0) {                                                    \
            ra0 = *(const float4*)(asrc0 + (size_t)(k0)*SEQ + m4);          \
            ra1 = *(const float4*)(asrc0 + (size_t)(k0)*SEQ + m4 + 64);     \
        } else {                                                            \
            ra0 = *(const float4*)(asrc1 + (k0));                           \
            ra1 = *(const float4*)(asrc1 + (size_t)64*K + (k0));            \
        }                                                                   \
        rb0 = *(const float4*)(bsrc + (k0));                                \
        rb1 = *(const float4*)(bsrc + (k0) + 4);                            \
    } while (0)

#define S_STORE(buf) do {                                                   \
        if (MODE == 0) {                                                    \
            *(float4*)&As[buf][c0*132 + m4]      = ra0;                     \
            *(float4*)&As[buf][c0*132 + m4 + 64] = ra1;                     \
        } else {                                                            \
            As[buf][(kqa+0)*132 + rr] = ra0.x; As[buf][(kqa+1)*132 + rr] = ra0.y; \
            As[buf][(kqa+2)*132 + rr] = ra0.z; As[buf][(kqa+3)*132 + rr] = ra0.w; \
            As[buf][(kqa+0)*132 + rr + 64] = ra1.x; As[buf][(kqa+1)*132 + rr + 64] = ra1.y; \
            As[buf][(kqa+2)*132 + rr + 64] = ra1.z; As[buf][(kqa+3)*132 + rr + 64] = ra1.w; \
        }                                                                   \
        Bs[buf][(kqb+0)*132 + nn] = rb0.x; Bs[buf][(kqb+1)*132 + nn] = rb0.y; \
        Bs[buf][(kqb+2)*132 + nn] = rb0.z; Bs[buf][(kqb+3)*132 + nn] = rb0.w; \
        Bs[buf][(kqb+4)*132 + nn] = rb1.x; Bs[buf][(kqb+5)*132 + nn] = rb1.y; \
        Bs[buf][(kqb+6)*132 + nn] = rb1.z; Bs[buf][(kqb+7)*132 + nn] = rb1.w; \
    } while (0)

    const int T = K / 16;
    G_LOAD(0);
    S_STORE(0);
    __syncthreads();

    for (int t = 0; t < T; ++t) {
        const int cur = t & 1;
        const bool more = (t + 1 < T);
        if (more) G_LOAD((t + 1) * 16);

#pragma unroll
        for (int k = 0; k < 16; ++k) {
            float4 a0 = *(const float4*)&As[cur][k*132 + tr*4];
            float4 a1 = *(const float4*)&As[cur][k*132 + tr*4 + 64];
            ulonglong2 bq0 = *(const ulonglong2*)&Bs[cur][k*132 + tc*4];
            ulonglong2 bq1 = *(const ulonglong2*)&Bs[cur][k*132 + tc*4 + 64];
            ull bp[4] = {bq0.x, bq0.y, bq1.x, bq1.y};
            float av[8] = {a0.x,a0.y,a0.z,a0.w,a1.x,a1.y,a1.z,a1.w};
#pragma unroll
            for (int i = 0; i < 8; ++i) {
                ull ad = dup2(av[i]);
#pragma unroll
                for (int j = 0; j < 4; ++j)
                    acc2[i][j] = ffma2(ad, bp[j], acc2[i][j]);
            }
        }

        if (more) {
            S_STORE((t + 1) & 1);
            __syncthreads();
        }
    }
#undef G_LOAD
#undef S_STORE

#pragma unroll
    for (int i = 0; i < 8; ++i) {
        int row = mBase + ((i < 4) ? (tr*4 + i) : (64 + tr*4 + (i-4)));
        float cv[8];
        unpack2(acc2[i][0], cv[0], cv[1]);
        unpack2(acc2[i][1], cv[2], cv[3]);
        unpack2(acc2[i][2], cv[4], cv[5]);
        unpack2(acc2[i][3], cv[6], cv[7]);
#pragma unroll
        for (int j = 0; j < 8; ++j) {
            int col = nBase + ((j < 4) ? (tc*4 + j) : (64 + tc*4 + (j-4)));
            float v = cv[j];
            if (MODE == 0) {
                v += g_binf[col];
                v = v - tanh_fast(v);
                g_inp[(size_t)row*N + col] = v;
            } else if (MODE == 1) {
                v += bias1[col] + bias2[col];
                g_xgate[(size_t)row*N + col] = v;
            } else {
                v += bias1[col];
                int b = row >> 10, l = row & 1023;
                Oext[(size_t)b*(OCC*SEQ) + (size_t)col*SEQ + l] = v;
            }
        }
    }
}

// ---------------- mbarrier helpers ----------------------------------------
__device__ __forceinline__ void mbar_init(uint32_t addr, unsigned count) {
    asm volatile("mbarrier.init.shared.b64 [%0], %1;" :: "r"(addr), "r"(count) : "memory");
}
__device__ __forceinline__ void mbar_expect_tx(uint32_t addr, unsigned bytes) {
    asm volatile("mbarrier.arrive.expect_tx.shared.b64 _, [%0], %1;"
                 :: "r"(addr), "r"(bytes) : "memory");
}
__device__ __forceinline__ void mbar_wait(uint32_t addr, unsigned parity) {
    unsigned done;
    asm volatile(
        "{\n\t.reg .pred P;\n\t"
        "mbarrier.try_wait.parity.acquire.cluster.shared::cta.b64 P, [%1], %2;\n\t"
        "selp.b32 %0, 1, 0, P;\n\t}"
        : "=r"(done) : "r"(addr), "r"(parity) : "memory");
    if (!done) {
        asm volatile(
            "{\n\t.reg .pred P;\n"
            "W%=:\n\t"
            "mbarrier.try_wait.parity.acquire.cluster.shared::cta.b64 P, [%0], %1, 0x989680;\n\t"
            "@P bra D%=;\n\t"
            "bra W%=;\n"
            "D%=:\n\t}"
            :: "r"(addr), "r"(parity) : "memory");
    }
}
// bulk DSMEM copy: local smem -> peer CTA smem, credits peer's mbarrier
__device__ __forceinline__ void bulk_copy_cluster(uint32_t dst, uint32_t src,
                                                  unsigned bytes, uint32_t mbar) {
    asm volatile(
        "cp.async.bulk.shared::cluster.shared::cta.mbarrier::complete_tx::bytes "
        "[%0], [%1], %2, [%3];"
        :: "r"(dst), "r"(src), "r"(bytes), "r"(mbar) : "memory");
}

// ---------------- clustered persistent RNN (R9 exact) --------------------
// 16 clusters x 8 CTAs. Cluster cl handles batches {2cl, 2cl+1}.
// CTA rank r owns hidden units j in [r*64, r*64+64).
// Weights (64 x 512) in registers (packed j-pairs, f32x2).
// Exchange: per step each CTA assembles its 128 result floats (64 j x 2
// batches) in a 512B staging buffer, then 8 threads issue one 512B
// cp.async.bulk each to the 8 cluster CTAs (incl. self). Each dest mbarrier
// sees 8 tx completions per phase.
// h buffer layout: [buf][src r: 132 floats = b0(64) b1(64) pad(4)].
#define SRCBLK 132            // floats per source block
#define HBUFW  (8*SRCBLK)     // 1056 floats per buffer
#define TXBYTES 4096u         // 8 sources x 512B

__global__ void __launch_bounds__(256,1) __cluster_dims__(8,1,1)
rnn_k(const float* __restrict__ w_hh) {
    __shared__ __align__(16) float h_s[2][HBUFW];     // [buf][8 src blocks]
    __shared__ __align__(16) float stage[2][128];     // double-buffered staging
    __shared__ __align__(8) ull mb_s[2];              // one mbarrier per buf

    const int tid  = threadIdx.x;
    const int warp = tid >> 5, lane = tid & 31;
    const int jq   = (warp << 1) | (lane & 1);   // 0..15: which quad of 4 j's
    const int kg   = lane >> 1;                  // 0..15: which 32-wide k slice
    uint32_t r; asm("mov.u32 %0, %%cluster_ctarank;" : "=r"(r));
    const int cl  = blockIdx.x >> 3;
    const int b0g = cl*2, b1g = cl*2 + 1;
    const int jcol  = (int)r*64 + jq*4;
    const int kbase = kg*32;

    // ---- weights into registers, packed per j-pair (lo=j0, hi=j1)
    ull w2[2][32];
#pragma unroll
    for (int jp = 0; jp < 2; ++jp) {
        const float* r0 = w_hh + (size_t)(jcol + jp*2) * RHH + kbase;
        const float* r1 = r0 + RHH;
#pragma unroll
        for (int q = 0; q < 8; ++q) {
            float4 a = *(const float4*)(r0 + q*4);
            float4 b = *(const float4*)(r1 + q*4);
            w2[jp][q*4+0] = pack2(a.x, b.x);
            w2[jp][q*4+1] = pack2(a.y, b.y);
            w2[jp][q*4+2] = pack2(a.z, b.z);
            w2[jp][q*4+3] = pack2(a.w, b.w);
        }
    }

    const uint32_t mb_local = (uint32_t)__cvta_generic_to_shared(&mb_s[0]);
    if (tid == 0) {
        mbar_init(mb_local,     1);
        mbar_init(mb_local + 8, 1);
        // arm first phases: mb[1] consumed at step 1, mb[0] at step 2
        mbar_expect_tx(mb_local + 8, TXBYTES);
        mbar_expect_tx(mb_local,     TXBYTES);
    }
    // zero h buffer 0
    for (int i = tid; i < HBUFW; i += 256) h_s[0][i] = 0.f;
    __syncthreads();
    asm volatile("barrier.cluster.arrive.aligned;" ::: "memory");
    asm volatile("barrier.cluster.wait.aligned;" ::: "memory");

    // peer addresses for bulk issue (thread tid<8 targets rank tid)
    const uint32_t h_base     = (uint32_t)__cvta_generic_to_shared(&h_s[0][0]);
    const uint32_t stage_base = (uint32_t)__cvta_generic_to_shared(&stage[0][0]);
    uint32_t hpeer = 0, mbpeer = 0;
    if (tid < 8) {
        asm("mapa.shared::cluster.u32 %0, %1, %2;"
            : "=r"(hpeer) : "r"(h_base), "r"((uint32_t)tid));
        asm("mapa.shared::cluster.u32 %0, %1, %2;"
            : "=r"(mbpeer) : "r"(mb_local), "r"((uint32_t)tid));
        hpeer += (uint32_t)(r * (SRCBLK*4));   // my block in peer's buffer
    }

    // prefetch xgate for l = 0
    float4 xg0 = *(const float4*)&g_xgate[(size_t)(b0g << 10)*RHH + jcol];
    float4 xg1 = *(const float4*)&g_xgate[(size_t)(b1g << 10)*RHH + jcol];

    for (int l = 0; l < SEQ; ++l) {
        const int p = l & 1;

        // ---- wait for h_l (bulks issued during step l-1); re-arm phase
        if (l) {
            unsigned par = (unsigned)(((l - 1) >> 1) & 1);
            mbar_wait(mb_local + p*8, par);
            if (tid == 0 && l < SEQ - 2)
                mbar_expect_tx(mb_local + p*8, TXBYTES);  // phase for step l+2
        }

        const float* hb0 = &h_s[p][(kg>>1)*SRCBLK + (kg&1)*32];
        const float* hb1 = hb0 + 64;

        ull a00 = 0ull, a01 = 0ull, a10 = 0ull, a11 = 0ull;  // [batch][jpair]
#pragma unroll
        for (int q = 0; q < 8; ++q) {
            float4 h0 = *(const float4*)(hb0 + q*4);
            float4 h1 = *(const float4*)(hb1 + q*4);
            ull hp;
            hp = dup2(h0.x); a00 = ffma2(hp, w2[0][q*4+0], a00); a01 = ffma2(hp, w2[1][q*4+0], a01);
            hp = dup2(h1.x); a10 = ffma2(hp, w2[0][q*4+0], a10); a11 = ffma2(hp, w2[1][q*4+0], a11);
            hp = dup2(h0.y); a00 = ffma2(hp, w2[0][q*4+1], a00); a01 = ffma2(hp, w2[1][q*4+1], a01);
            hp = dup2(h1.y); a10 = ffma2(hp, w2[0][q*4+1], a10); a11 = ffma2(hp, w2[1][q*4+1], a11);
            hp = dup2(h0.z); a00 = ffma2(hp, w2[0][q*4+2], a00); a01 = ffma2(hp, w2[1][q*4+2], a01);
            hp = dup2(h1.z); a10 = ffma2(hp, w2[0][q*4+2], a10); a11 = ffma2(hp, w2[1][q*4+2], a11);
            hp = dup2(h0.w); a00 = ffma2(hp, w2[0][q*4+3], a00); a01 = ffma2(hp, w2[1][q*4+3], a01);
            hp = dup2(h1.w); a10 = ffma2(hp, w2[0][q*4+3], a10); a11 = ffma2(hp, w2[1][q*4+3], a11);
        }

        // butterfly reduce over kg (lane bits 1..4); jq bit untouched
#pragma unroll
        for (int m = 2; m <= 16; m <<= 1) {
            a00 = addf2(a00, __shfl_xor_sync(0xffffffffu, a00, m));
            a01 = addf2(a01, __shfl_xor_sync(0xffffffffu, a01, m));
            a10 = addf2(a10, __shfl_xor_sync(0xffffffffu, a10, m));
            a11 = addf2(a11, __shfl_xor_sync(0xffffffffu, a11, m));
        }

        float s0, s1;
        unpack2(a00, s0, s1);
        float h00 = tanh_fast(s0 + xg0.x), h01 = tanh_fast(s1 + xg0.y);
        unpack2(a01, s0, s1);
        float h02 = tanh_fast(s0 + xg0.z), h03 = tanh_fast(s1 + xg0.w);
        unpack2(a10, s0, s1);
        float h10 = tanh_fast(s0 + xg1.x), h11 = tanh_fast(s1 + xg1.y);
        unpack2(a11, s0, s1);
        float h12 = tanh_fast(s0 + xg1.z), h13 = tanh_fast(s1 + xg1.w);

        // stage this CTA's 128 result floats (writers: lanes 0,1 per warp)
        if (lane < 2) {
            *(float4*)&stage[p][jq*4]      = make_float4(h00, h01, h02, h03);
            *(float4*)&stage[p][64 + jq*4] = make_float4(h10, h11, h12, h13);
        }
        if (kg == 8) {  // persist outputs (lanes 16,17 per warp)
            size_t row0 = (size_t)((b0g << 10) | l);
            size_t row1 = (size_t)((b1g << 10) | l);
            *(float4*)&g_outs[row0*RHH + jcol] = make_float4(h00, h01, h02, h03);
            *(float4*)&g_outs[row1*RHH + jcol] = make_float4(h10, h11, h12, h13);
        }

        if (l < SEQ - 1) {
            __syncthreads();     // staging complete; all reads of buf p done
            if (tid < 8) {
                asm volatile("fence.proxy.async.shared::cta;" ::: "memory");
                bulk_copy_cluster(hpeer + (uint32_t)((p ^ 1) * (HBUFW*4)),
                                  stage_base + (uint32_t)(p * 512),
                                  512u,
                                  mbpeer + (uint32_t)((p ^ 1) * 8));
            }
            // prefetch next step's xgate (overlaps bulk propagation)
            int l1 = l + 1;
            xg0 = *(const float4*)&g_xgate[(size_t)((b0g << 10) | l1)*RHH + jcol];
            xg1 = *(const float4*)&g_xgate[(size_t)((b1g << 10) | l1)*RHH + jcol];
        }
    }

    // keep SMEM alive until all peers are done with remote ops
    asm volatile("barrier.cluster.arrive.aligned;" ::: "memory");
    asm volatile("barrier.cluster.wait.aligned;" ::: "memory");
}

// ---------------- launch ---------------------------------------------------
extern "C" void kernel_launch(void* const* d_in, const int* in_sizes, int n_in,
                              void* d_out, int out_size) {
    const float* x     = (const float*)d_in[0];
    const float* gamma = (const float*)d_in[1];
    const float* beta  = (const float*)d_in[2];
    const float* w_in  = (const float*)d_in[3];
    const float* b_in  = (const float*)d_in[4];
    const float* w_ih  = (const float*)d_in[5];
    const float* b_ih  = (const float*)d_in[6];
    const float* w_hh  = (const float*)d_in[7];
    const float* b_hh  = (const float*)d_in[8];
    const float* w_out = (const float*)d_in[9];
    const float* b_out = (const float*)d_in[10];
    float* out = (float*)d_out;

    bn_stats_k<<<CH, 256>>>(x, gamma, beta);
    fold_k<<<RINN, 128>>>(w_in, b_in);

    dim3 g1(MTOT/128, RINN/128);   // (256, 2)
    gemm_k<0, RINN, CH><<<g1, 256>>>(x, nullptr, nullptr, nullptr, nullptr);

    dim3 g2(MTOT/128, RHH/128);    // (256, 4)
    gemm_k<1, RHH, RINN><<<g2, 256>>>(nullptr, w_ih, b_ih, b_hh, nullptr);

    rnn_k<<<128, 256>>>(w_hh);

    dim3 g4(MTOT/128, OCC/128);    // (256, 1)
    gemm_k<2, OCC, RHH><<<g4, 256>>>(nullptr, w_out, b_out, nullptr, out);
}